// round 15
// baseline (speedup 1.0000x reference)
#include <cuda_runtime.h>
#include <cstdint>
#include <cstddef>

// ----------------------------------------------------------------------------
// Round 14 = R13 + C1 merged into G2 (j-split C1, warp-private h handoff,
//            removes barrier B3) + 132-float row padding on partial buffers
//            (conflict-free C1-j reads).
//   a <- a + W2^T tanh([x_t; a] @ W1 + b1) + b2,  512 steps.
// 32 clusters x 4 CTAs; cluster owns 8 batch rows; CTA rank owns hidden slice
// [128r, 128r+128). G1 weights in registers (w1x[16]+w1a[16] ulonglong2/thread).
//
// Per-step: G1a(acc into hp_x) | B2 |
//   [C1-j: lane=(row,j4) sums 8 hp_x bufs + b1, tanh -> h_s(own j-chunk);
//    __syncwarp; G2: same warp contracts its j-chunk from h_s] | B4 |
//   C2(combine 8 hp bufs, publish .cg) | cluster.arrive |
//   G1x(t+1) rows 0-3 | cluster.wait | fold ldcg x4 | G1x(t+1) rows 4-7 |
//   fold combine + x stage | B1
// ----------------------------------------------------------------------------

#define T_STEPS  512
#define DIN      128
#define DST      128
#define DHID     512
#define NCL      32
#define CSZ      4
#define ROWS     8
#define NTHREADS 256

#define HPAD 132      // padded row stride (floats) for partial bufs + h_s
#define HBUF 1056     // 8 * HPAD, one partial buffer

typedef unsigned long long u64;

#define FMA2(acc, s, w) asm("fma.rn.f32x2 %0, %1, %2, %0;" : "+l"(acc) : "l"(s), "l"(w))
#define PACK2(d, v)     asm("mov.b64 %0, {%1, %1};"        : "=l"(d)   : "r"(__float_as_uint(v)))

// double-buffered per-rank partial states (1 MB static scratch)
__device__ float g_pstate[2][NCL][CSZ][ROWS][DST];

// smem layout (floats):
//   W2s  [128][128]   @ 0            (65536 B)
//   hp   [8][8][132]  @ 16384        (33792 B)  G2 partials (padded)
//   hp_x [8][8][132]  @ 24832        (33792 B)  G1x+G1a preact partials (padded)
//   a_s  [8][128]     @ 33280        ( 4096 B)
//   x2   [2][8][128]  @ 34304        ( 8192 B)
//   h_s  [8][132]     @ 36352        ( 4224 B)  (padded)
#define OFF_HP   16384
#define OFF_HPX  24832
#define OFF_AS   33280
#define OFF_X2   34304
#define OFF_HS   36352
#define SMEM_FLOATS 37408    // 149632 B

static __device__ __forceinline__ float4 f4add(float4 a, float4 b) {
    return make_float4(a.x + b.x, a.y + b.y, a.z + b.z, a.w + b.w);
}

// tanh(x) = 1 - 2/(e^{2x}+1) via ex2.approx/rcp.approx. Abs err ~1e-7.
static __device__ __forceinline__ float tanh_fast(float v) {
    float e, r;
    asm("ex2.approx.f32 %0, %1;" : "=f"(e) : "f"(v * 2.8853900817779268f));
    asm("rcp.approx.f32 %0, %1;" : "=f"(r) : "f"(e + 1.0f));
    return fmaf(-2.0f, r, 1.0f);
}

// 16-k x 4-row x 4-col GEMM partial, register weights, fresh write.
// act rows stride 128; out rows stride HPAD.
static __device__ __forceinline__ void gemm16_rows(
    const float* __restrict__ act, const ulonglong2* __restrict__ w,
    float* __restrict__ outp, int rlo)
{
    ulonglong2 acc[4];
    #pragma unroll
    for (int r = 0; r < 4; ++r) { acc[r].x = 0ull; acc[r].y = 0ull; }
    #pragma unroll
    for (int kb = 0; kb < 4; ++kb) {
        float4 av[4];
        #pragma unroll
        for (int r = 0; r < 4; ++r)
            av[r] = *(const float4*)(act + (rlo + r) * 128 + kb * 4);
        #pragma unroll
        for (int kk = 0; kk < 4; ++kk) {
            const ulonglong2 ww = w[kb * 4 + kk];
            #pragma unroll
            for (int r = 0; r < 4; ++r) {
                float s = (kk == 0) ? av[r].x : (kk == 1) ? av[r].y
                        : (kk == 2) ? av[r].z : av[r].w;
                u64 sp; PACK2(sp, s);
                FMA2(acc[r].x, sp, ww.x);
                FMA2(acc[r].y, sp, ww.y);
            }
        }
    }
    #pragma unroll
    for (int r = 0; r < 4; ++r)
        *(ulonglong2*)(outp + (rlo + r) * HPAD) = acc[r];
}

// Same, accumulating on top of existing buffer contents (G1x partials).
static __device__ __forceinline__ void gemm16_rows_acc(
    const float* __restrict__ act, const ulonglong2* __restrict__ w,
    float* __restrict__ outp, int rlo)
{
    ulonglong2 acc[4];
    #pragma unroll
    for (int r = 0; r < 4; ++r)
        acc[r] = *(const ulonglong2*)(outp + (rlo + r) * HPAD);
    #pragma unroll
    for (int kb = 0; kb < 4; ++kb) {
        float4 av[4];
        #pragma unroll
        for (int r = 0; r < 4; ++r)
            av[r] = *(const float4*)(act + (rlo + r) * 128 + kb * 4);
        #pragma unroll
        for (int kk = 0; kk < 4; ++kk) {
            const ulonglong2 ww = w[kb * 4 + kk];
            #pragma unroll
            for (int r = 0; r < 4; ++r) {
                float s = (kk == 0) ? av[r].x : (kk == 1) ? av[r].y
                        : (kk == 2) ? av[r].z : av[r].w;
                u64 sp; PACK2(sp, s);
                FMA2(acc[r].x, sp, ww.x);
                FMA2(acc[r].y, sp, ww.y);
            }
        }
    }
    #pragma unroll
    for (int r = 0; r < 4; ++r)
        *(ulonglong2*)(outp + (rlo + r) * HPAD) = acc[r];
}

__global__ void __cluster_dims__(CSZ, 1, 1) __launch_bounds__(NTHREADS, 1)
rnn_kernel(const float* __restrict__ x,  const float* __restrict__ a0,
           const float* __restrict__ W1, const float* __restrict__ b1,
           const float* __restrict__ W2, const float* __restrict__ b2,
           float* __restrict__ out)
{
    extern __shared__ float sm[];
    float* W2s  = sm;
    float* hp   = sm + OFF_HP;
    float* hp_x = sm + OFF_HPX;
    float* a_s  = sm + OFF_AS;
    float* x2   = sm + OFF_X2;   // [2][8][128]
    float* h_s  = sm + OFF_HS;   // [8][HPAD]

    const int tid   = threadIdx.x;
    const int lane  = tid & 31;
    const int wid   = tid >> 5;
    const int bx    = blockIdx.x;
    const int crank = bx & (CSZ - 1);
    const int gcl   = bx >> 2;
    const int rowbase = gcl * ROWS;
    const int jbase   = crank * 128;
    const int cj      = lane * 4;

    // ---- G1 weights into registers ----
    ulonglong2 w1x[16], w1a[16];
    {
        const float* ws = W1 + (size_t)(16 * wid) * DHID + jbase + cj;
        #pragma unroll
        for (int r = 0; r < 16; ++r)
            w1x[r] = *(const ulonglong2*)(ws + (size_t)r * DHID);
        const float* wa = W1 + (size_t)(128 + 16 * wid) * DHID + jbase + cj;
        #pragma unroll
        for (int r = 0; r < 16; ++r)
            w1a[r] = *(const ulonglong2*)(wa + (size_t)r * DHID);
    }

    // ---- prologue: W2 slice, a0, x(0)->x2[0], x(1)->x2[1], xr=x(2) ----
    for (int i = tid; i < 4096; i += NTHREADS)
        ((float4*)W2s)[i] = ((const float4*)(W2 + (size_t)jbase * DST))[i];
    for (int i = tid; i < 256; i += NTHREADS)
        ((float4*)a_s)[i] = ((const float4*)(a0 + (size_t)rowbase * DST))[i];
    for (int i = tid; i < 256; i += NTHREADS) {
        int r = i >> 5, c4 = (i & 31) << 2;
        *(float4*)(x2 + r * 128 + c4) =
            *(const float4*)(x + (size_t)(rowbase + r) * (size_t)(T_STEPS * DIN) + c4);
    }

    const int crow = wid;                 // this warp's batch row (C2/fold)
    const float4 rb2 = *(const float4*)(b2 + cj);

    // C1-j lane mapping: r8 = row, j4 = j-quad within this warp's 16-j chunk
    const int r8 = lane >> 2;
    const int j4 = lane & 3;
    const int joff = wid * 16 + j4 * 4;   // j offset within CTA slice
    const float4 rb1j = *(const float4*)(b1 + jbase + joff);
    const float* c1_rd = hp_x + r8 * HPAD + joff;   // + q*HBUF
    float*       c1_wr = h_s  + r8 * HPAD + joff;

    const float* xrow = x + (size_t)(rowbase + crow) * (size_t)(T_STEPS * DIN) + cj;
    *(float4*)(x2 + 1024 + crow * 128 + cj) = *(const float4*)(xrow + DIN);  // x(1)
    float4 xr = *(const float4*)(xrow + 2 * DIN);                            // x(2)

    const float* g2_wr = W2s + (wid * 16) * 128 + cj;
    float* hpo  = hp   + wid * HBUF + cj;
    float* hpxo = hp_x + wid * HBUF + cj;

    __syncthreads();

    // ---- G1x for step 0 ----
    gemm16_rows(x2 + wid * 16, w1x, hpxo, 0);
    gemm16_rows(x2 + wid * 16, w1x, hpxo, 4);
    __syncthreads();   // B1 (step 0 entry)

    for (int t = 0; t < T_STEPS; ++t) {
        // ---- G1a: accumulate a-part on top of G1x partials in hp_x ----
        gemm16_rows_acc(a_s + wid * 16, w1a, hpxo, 0);
        gemm16_rows_acc(a_s + wid * 16, w1a, hpxo, 4);
        __syncthreads();   // B2

        // ---- C1-j (warp-private): sum 8 hp_x bufs + b1 -> tanh -> h_s chunk ----
        {
            float4 s = *(const float4*)(c1_rd);
            #pragma unroll
            for (int q = 1; q < 8; ++q)
                s = f4add(s, *(const float4*)(c1_rd + q * HBUF));
            float4 hv;
            hv.x = tanh_fast(s.x + rb1j.x);
            hv.y = tanh_fast(s.y + rb1j.y);
            hv.z = tanh_fast(s.z + rb1j.z);
            hv.w = tanh_fast(s.w + rb1j.w);
            *(float4*)(c1_wr) = hv;
        }
        __syncwarp();      // h chunk visible within this warp only — sufficient

        // ---- G2: same warp contracts its own j-chunk from h_s ----
        {
            ulonglong2 acc[ROWS];
            #pragma unroll
            for (int r = 0; r < ROWS; ++r) { acc[r].x = 0ull; acc[r].y = 0ull; }
            const float* act2 = h_s + wid * 16;
            #pragma unroll
            for (int kb = 0; kb < 4; ++kb) {
                #pragma unroll
                for (int half = 0; half < 2; ++half) {
                    float4 av[4];
                    #pragma unroll
                    for (int r = 0; r < 4; ++r)
                        av[r] = *(const float4*)(act2 + (half * 4 + r) * HPAD + kb * 4);
                    const float* wk = g2_wr + kb * 4 * 128;
                    #pragma unroll
                    for (int kk = 0; kk < 4; ++kk) {
                        const ulonglong2 ww = *(const ulonglong2*)(wk + kk * 128);
                        #pragma unroll
                        for (int r = 0; r < 4; ++r) {
                            float s = (kk == 0) ? av[r].x : (kk == 1) ? av[r].y
                                    : (kk == 2) ? av[r].z : av[r].w;
                            u64 sp; PACK2(sp, s);
                            FMA2(acc[half * 4 + r].x, sp, ww.x);
                            FMA2(acc[half * 4 + r].y, sp, ww.y);
                        }
                    }
                }
            }
            #pragma unroll
            for (int r = 0; r < ROWS; ++r)
                *(ulonglong2*)(hpo + r * HPAD) = acc[r];
        }
        __syncthreads();   // B4

        // ---- C2: combine 8 G2 bufs -> publish my rank's state partial ----
        {
            const float* hb = hp + crow * HPAD + cj;
            float4 s = *(const float4*)(hb);
            #pragma unroll
            for (int q = 1; q < 8; ++q)
                s = f4add(s, *(const float4*)(hb + q * HBUF));
            __stcg((float4*)&g_pstate[t & 1][gcl][crank][crow][cj], s);
        }
        asm volatile("barrier.cluster.arrive.aligned;" ::: "memory");

        // ---- G1x(t+1) part A: rows 0-3, hides the barrier settle ----
        const float* xb = x2 + ((t + 1) & 1) * 1024 + wid * 16;
        if (t + 1 < T_STEPS)
            gemm16_rows(xb, w1x, hpxo, 0);

        asm volatile("barrier.cluster.wait.aligned;" ::: "memory");

        // ---- fold loads (valid after wait), hidden under G1x part B ----
        float4 p0 = __ldcg((const float4*)&g_pstate[t & 1][gcl][0][crow][cj]);
        float4 p1 = __ldcg((const float4*)&g_pstate[t & 1][gcl][1][crow][cj]);
        float4 p2 = __ldcg((const float4*)&g_pstate[t & 1][gcl][2][crow][cj]);
        float4 p3 = __ldcg((const float4*)&g_pstate[t & 1][gcl][3][crow][cj]);

        if (t + 1 < T_STEPS)
            gemm16_rows(xb, w1x, hpxo, 4);

        // ---- fold combine: a(t+1) = a(t) + sum(partials) + b2 ----
        {
            float4 acc = f4add(f4add(p0, p1), f4add(p2, p3));
            float4 av = *(float4*)(a_s + crow * DST + cj);
            av.x += acc.x + rb2.x;  av.y += acc.y + rb2.y;
            av.z += acc.z + rb2.z;  av.w += acc.w + rb2.w;
            *(float4*)(a_s + crow * DST + cj) = av;
        }
        // ---- stage x(t+2); prefetch x(t+3) ----
        if (t + 2 < T_STEPS) {
            *(float4*)(x2 + (t & 1) * 1024 + crow * 128 + cj) = xr;
            if (t + 3 < T_STEPS)
                xr = *(const float4*)(xrow + (size_t)(t + 3) * DIN);
        }
        __syncthreads();   // B1
    }

    // ---- epilogue: a_s holds a(T); rank 0 writes out ----
    if (crank == 0) {
        float4 av = *(float4*)(a_s + crow * DST + cj);
        *(float4*)(out + (size_t)(rowbase + crow) * DST + cj) = av;
    }
}

extern "C" void kernel_launch(void* const* d_in, const int* in_sizes, int n_in,
                              void* d_out, int out_size) {
    const float* x  = (const float*)d_in[0];
    const float* a0 = (const float*)d_in[1];
    const float* W1 = (const float*)d_in[2];
    const float* b1 = (const float*)d_in[3];
    const float* W2 = (const float*)d_in[4];
    const float* b2 = (const float*)d_in[5];
    float* out = (float*)d_out;

    const size_t smem = SMEM_FLOATS * sizeof(float);   // 149632 B
    cudaFuncSetAttribute(rnn_kernel, cudaFuncAttributeMaxDynamicSharedMemorySize,
                         (int)smem);
    rnn_kernel<<<NCL * CSZ, NTHREADS, smem>>>(x, a0, W1, b1, W2, b2, out);
}